// round 2
// baseline (speedup 1.0000x reference)
#include <cuda_runtime.h>
#include <cstdint>

#define NN   131072
#define CCH  128
#define SSC  6
#define BBL  4
#define EE   131072
#define ELL  32768

// Scratch buffers (device globals — no runtime allocation allowed)
__device__ float g_temp [NN * CCH];
__device__ float g_feat2[NN * CCH];
__device__ float g_h2   [NN * CCH];

__device__ __forceinline__ uint32_t f2tf(float x) {
    uint32_t r;
    asm("cvt.rna.tf32.f32 %0, %1;" : "=r"(r) : "f"(x));
    return r;
}

__device__ __forceinline__ void mma8(float* d, uint32_t a0, uint32_t a1, uint32_t a2, uint32_t a3,
                                     uint32_t b0, uint32_t b1) {
    asm volatile(
        "mma.sync.aligned.m16n8k8.row.col.f32.tf32.tf32.f32 "
        "{%0,%1,%2,%3}, {%4,%5,%6,%7}, {%8,%9}, {%0,%1,%2,%3};"
        : "+f"(d[0]), "+f"(d[1]), "+f"(d[2]), "+f"(d[3])
        : "r"(a0), "r"(a1), "r"(a2), "r"(a3), "r"(b0), "r"(b1));
}

__device__ __forceinline__ void red2(float* p, float x, float y) {
    asm volatile("red.global.add.v2.f32 [%0], {%1, %2};"
                 :: "l"(p), "f"(x), "f"(y) : "memory");
}

// ---------------------------------------------------------------------------
// gather -> [128 rows x 128 cols, K=128] tf32 MMA -> scatter (atomic or store)
// grid = nrows/128 blocks, 256 threads (8 warps), each warp owns 16 M-rows.
// Smem: As [128][132] (m,k)   Ws [128][132] (n,k)  -> conflict-free frag loads
// ---------------------------------------------------------------------------
template <bool IDENTITY>
__global__ void __launch_bounds__(256, 1)
gemm_scatter(const float* __restrict__ A, const float* __restrict__ W,
             float* __restrict__ out,
             const int* __restrict__ u_idx, const int* __restrict__ v_idx) {
    extern __shared__ uint32_t sm[];
    uint32_t* As = sm;               // [128][132]  A[m][k]
    uint32_t* Ws = sm + 128 * 132;   // [128][132]  W^T: Ws[n][k] = W[k][n]
    __shared__ int su[128];

    const int tid  = threadIdx.x;
    const int warp = tid >> 5, lane = tid & 31;
    const int g    = lane >> 2, tg = lane & 3;
    const int tile0 = blockIdx.x * 128;

    // Stage W transposed (coalesced global reads, tf32-convert on the way in)
    for (int i = tid; i < 4096; i += 256) {
        int n = i & 127, r = i >> 7;   // r in [0,32): k-groups of 4
#pragma unroll
        for (int j = 0; j < 4; j++) {
            int k = 4 * r + j;
            Ws[n * 132 + k] = f2tf(W[k * 128 + n]);
        }
    }
    // Gather A rows (vectorized 16B loads; random rows hit L2)
    for (int i = tid; i < 4096; i += 256) {
        int r = i >> 5, s = i & 31;
        int src = IDENTITY ? (tile0 + r) : v_idx[tile0 + r];
        float4 av = reinterpret_cast<const float4*>(A)[src * 32 + s];
        uint32_t* p = As + r * 132 + s * 4;
        p[0] = f2tf(av.x); p[1] = f2tf(av.y); p[2] = f2tf(av.z); p[3] = f2tf(av.w);
    }
    if (tid < 128) su[tid] = IDENTITY ? (tile0 + tid) : u_idx[tile0 + tid];
    __syncthreads();

    float acc[16][4];
#pragma unroll
    for (int nt = 0; nt < 16; nt++) {
        acc[nt][0] = acc[nt][1] = acc[nt][2] = acc[nt][3] = 0.f;
    }

    const int arow = warp * 16 + g;
#pragma unroll
    for (int k0 = 0; k0 < 128; k0 += 8) {
        uint32_t a0 = As[arow * 132 + k0 + tg];
        uint32_t a1 = As[(arow + 8) * 132 + k0 + tg];
        uint32_t a2 = As[arow * 132 + k0 + tg + 4];
        uint32_t a3 = As[(arow + 8) * 132 + k0 + tg + 4];
#pragma unroll
        for (int nt = 0; nt < 16; nt++) {
            uint32_t b0 = Ws[(nt * 8 + g) * 132 + k0 + tg];
            uint32_t b1 = Ws[(nt * 8 + g) * 132 + k0 + tg + 4];
            mma8(acc[nt], a0, a1, a2, a3, b0, b1);
        }
    }

    const int r0 = warp * 16 + g, r1 = r0 + 8;
    const int d0 = su[r0], d1 = su[r1];
#pragma unroll
    for (int nt = 0; nt < 16; nt++) {
        int col = nt * 8 + 2 * tg;
        float* p0 = out + (size_t)d0 * 128 + col;
        float* p1 = out + (size_t)d1 * 128 + col;
        if (IDENTITY) {
            *reinterpret_cast<float2*>(p0) = make_float2(acc[nt][0], acc[nt][1]);
            *reinterpret_cast<float2*>(p1) = make_float2(acc[nt][2], acc[nt][3]);
        } else {
            red2(p0, acc[nt][0], acc[nt][1]);
            red2(p1, acc[nt][2], acc[nt][3]);
        }
    }
}

// ---------------------------------------------------------------------------
// GroupNorm(num_groups=1) over 128 channels, warp-per-row.
// MODE 0: GN   MODE 1: relu(GN)   MODE 2: relu(GN + res)
// ---------------------------------------------------------------------------
template <int MODE>
__global__ void __launch_bounds__(128)
gn_kernel(const float* __restrict__ in, const float* __restrict__ gamma,
          const float* __restrict__ beta, const float* __restrict__ res,
          float* __restrict__ out) {
    const int warp = threadIdx.x >> 5, lane = threadIdx.x & 31;
    const size_t row = (size_t)blockIdx.x * 4 + warp;
    float4 x = reinterpret_cast<const float4*>(in)[row * 32 + lane];
    float s = x.x + x.y + x.z + x.w;
    float q = x.x * x.x + x.y * x.y + x.z * x.z + x.w * x.w;
#pragma unroll
    for (int o = 16; o > 0; o >>= 1) {
        s += __shfl_xor_sync(0xffffffffu, s, o);
        q += __shfl_xor_sync(0xffffffffu, q, o);
    }
    float mu  = s * (1.f / 128.f);
    float var = q * (1.f / 128.f) - mu * mu;
    float inv = rsqrtf(var + 1e-5f);
    float4 gm = reinterpret_cast<const float4*>(gamma)[lane];
    float4 bt = reinterpret_cast<const float4*>(beta)[lane];
    float4 y;
    y.x = (x.x - mu) * inv * gm.x + bt.x;
    y.y = (x.y - mu) * inv * gm.y + bt.y;
    y.z = (x.z - mu) * inv * gm.z + bt.z;
    y.w = (x.w - mu) * inv * gm.w + bt.w;
    if (MODE == 2) {
        float4 rv = reinterpret_cast<const float4*>(res)[row * 32 + lane];
        y.x += rv.x; y.y += rv.y; y.z += rv.z; y.w += rv.w;
    }
    if (MODE >= 1) {
        y.x = fmaxf(y.x, 0.f); y.y = fmaxf(y.y, 0.f);
        y.z = fmaxf(y.z, 0.f); y.w = fmaxf(y.w, 0.f);
    }
    reinterpret_cast<float4*>(out)[row * 32 + lane] = y;
}

// ---------------------------------------------------------------------------
// h1 = relu(ctrs @ W0a + b0a), h2 = relu(feats @ W0b + b0b)   (K=2 matvec)
// ---------------------------------------------------------------------------
__global__ void __launch_bounds__(256)
mlp0_kernel(const float* __restrict__ ctrs, const float* __restrict__ feats,
            const float* __restrict__ w0a, const float* __restrict__ b0a,
            const float* __restrict__ w0b, const float* __restrict__ b0b,
            float* __restrict__ h1, float* __restrict__ h2) {
    const int idx = blockIdx.x * 256 + threadIdx.x;  // over N*32 float4 slots
    const int n = idx >> 5, s = idx & 31;
    float c0 = ctrs[n * 2], c1 = ctrs[n * 2 + 1];
    float e0 = feats[n * 2], e1 = feats[n * 2 + 1];

    float4 wa0 = reinterpret_cast<const float4*>(w0a)[s];
    float4 wa1 = reinterpret_cast<const float4*>(w0a)[32 + s];
    float4 ba  = reinterpret_cast<const float4*>(b0a)[s];
    float4 o1;
    o1.x = fmaxf(c0 * wa0.x + c1 * wa1.x + ba.x, 0.f);
    o1.y = fmaxf(c0 * wa0.y + c1 * wa1.y + ba.y, 0.f);
    o1.z = fmaxf(c0 * wa0.z + c1 * wa1.z + ba.z, 0.f);
    o1.w = fmaxf(c0 * wa0.w + c1 * wa1.w + ba.w, 0.f);
    reinterpret_cast<float4*>(h1)[idx] = o1;

    float4 wb0 = reinterpret_cast<const float4*>(w0b)[s];
    float4 wb1 = reinterpret_cast<const float4*>(w0b)[32 + s];
    float4 bb  = reinterpret_cast<const float4*>(b0b)[s];
    float4 o2;
    o2.x = fmaxf(e0 * wb0.x + e1 * wb1.x + bb.x, 0.f);
    o2.y = fmaxf(e0 * wb0.y + e1 * wb1.y + bb.y, 0.f);
    o2.z = fmaxf(e0 * wb0.z + e1 * wb1.z + bb.z, 0.f);
    o2.w = fmaxf(e0 * wb0.w + e1 * wb1.w + bb.w, 0.f);
    reinterpret_cast<float4*>(h2)[idx] = o2;
}

// ---------------------------------------------------------------------------

extern "C" void kernel_launch(void* const* d_in, const int* in_sizes, int n_in,
                              void* d_out, int out_size) {
    const float* ctrs   = (const float*)d_in[0];
    const float* feats  = (const float*)d_in[1];
    const int* pre_u    = (const int*)d_in[2];
    const int* pre_v    = (const int*)d_in[3];
    const int* suc_u    = (const int*)d_in[4];
    const int* suc_v    = (const int*)d_in[5];
    const int* left_u   = (const int*)d_in[6];
    const int* left_v   = (const int*)d_in[7];
    const int* right_u  = (const int*)d_in[8];
    const int* right_v  = (const int*)d_in[9];
    const float* ic_w0  = (const float*)d_in[10];
    const float* ic_b0  = (const float*)d_in[11];
    const float* ic_w1  = (const float*)d_in[12];
    const float* ic_g   = (const float*)d_in[13];
    const float* ic_bt  = (const float*)d_in[14];
    const float* if_w0  = (const float*)d_in[15];
    const float* if_b0  = (const float*)d_in[16];
    const float* if_w1  = (const float*)d_in[17];
    const float* if_g   = (const float*)d_in[18];
    const float* if_bt  = (const float*)d_in[19];
    const float* ctr_w  = (const float*)d_in[20];
    const float* pre_w  = (const float*)d_in[21];
    const float* suc_w  = (const float*)d_in[22];
    const float* left_w = (const float*)d_in[23];
    const float* right_w= (const float*)d_in[24];
    const float* norm_g = (const float*)d_in[25];
    const float* norm_b = (const float*)d_in[26];
    const float* ctr2_w = (const float*)d_in[27];
    const float* ctr2_g = (const float*)d_in[28];
    const float* ctr2_b = (const float*)d_in[29];

    float* feat = (float*)d_out;
    float *temp, *feat2, *h2;
    cudaGetSymbolAddress((void**)&temp,  g_temp);
    cudaGetSymbolAddress((void**)&feat2, g_feat2);
    cudaGetSymbolAddress((void**)&h2,    g_h2);

    constexpr int SMEMB = 2 * 128 * 132 * 4;  // 135168 bytes
    cudaFuncSetAttribute((const void*)gemm_scatter<true>,
                         cudaFuncAttributeMaxDynamicSharedMemorySize, SMEMB);
    cudaFuncSetAttribute((const void*)gemm_scatter<false>,
                         cudaFuncAttributeMaxDynamicSharedMemorySize, SMEMB);

    // ---- input MLPs: feat = relu(GN(h1@ic_w1) + GN(h2@if_w1)) ----
    mlp0_kernel<<<NN * 32 / 256, 256>>>(ctrs, feats, ic_w0, ic_b0, if_w0, if_b0,
                                        feat2, h2);
    gemm_scatter<true><<<NN / 128, 256, SMEMB>>>(feat2, ic_w1, temp, nullptr, nullptr);
    gn_kernel<0><<<NN / 4, 128>>>(temp, ic_g, ic_bt, nullptr, feat2);   // f1 -> feat2
    gemm_scatter<true><<<NN / 128, 256, SMEMB>>>(h2, if_w1, temp, nullptr, nullptr);
    gn_kernel<2><<<NN / 4, 128>>>(temp, if_g, if_bt, feat2, feat);      // feat = relu(f2+f1)

    // ---- 4 residual fusion blocks ----
    for (int i = 0; i < BBL; i++) {
        // temp = feat @ ctr_w[i]   (plain store: doubles as the zero-init)
        gemm_scatter<true><<<NN / 128, 256, SMEMB>>>(feat, ctr_w + i * 16384, temp,
                                                     nullptr, nullptr);
        for (int s = 0; s < SSC; s++)
            gemm_scatter<false><<<EE / 128, 256, SMEMB>>>(
                feat, pre_w + (i * SSC + s) * 16384, temp,
                pre_u + s * EE, pre_v + s * EE);
        for (int s = 0; s < SSC; s++)
            gemm_scatter<false><<<EE / 128, 256, SMEMB>>>(
                feat, suc_w + (i * SSC + s) * 16384, temp,
                suc_u + s * EE, suc_v + s * EE);
        gemm_scatter<false><<<ELL / 128, 256, SMEMB>>>(
            feat, left_w + i * 16384, temp, left_u, left_v);
        gemm_scatter<false><<<ELL / 128, 256, SMEMB>>>(
            feat, right_w + i * 16384, temp, right_u, right_v);

        // feat2 = relu(GN(temp))
        gn_kernel<1><<<NN / 4, 128>>>(temp, norm_g + i * 128, norm_b + i * 128,
                                      nullptr, feat2);
        // temp = feat2 @ ctr2_w[i]
        gemm_scatter<true><<<NN / 128, 256, SMEMB>>>(feat2, ctr2_w + i * 16384, temp,
                                                     nullptr, nullptr);
        // feat = relu(GN(temp) + feat)   (in-place residual, row-local)
        gn_kernel<2><<<NN / 4, 128>>>(temp, ctr2_g + i * 128, ctr2_b + i * 128,
                                      feat, feat);
    }
}

// round 4
// speedup vs baseline: 1.0797x; 1.0797x over previous
#include <cuda_runtime.h>
#include <cstdint>

#define NN   131072
#define CCH  128
#define SSC  6
#define BBL  4
#define EE   131072
#define ELL  32768

// Scratch buffers (device globals — no runtime allocation allowed)
__device__ float g_temp [NN * CCH];
__device__ float g_feat2[NN * CCH];
__device__ float g_h2   [NN * CCH];

__device__ __forceinline__ uint32_t f2tf(float x) {
    uint32_t r;
    asm("cvt.rna.tf32.f32 %0, %1;" : "=r"(r) : "f"(x));
    return r;
}

__device__ __forceinline__ void mma8(float* d, uint32_t a0, uint32_t a1, uint32_t a2, uint32_t a3,
                                     uint32_t b0, uint32_t b1) {
    asm volatile(
        "mma.sync.aligned.m16n8k8.row.col.f32.tf32.tf32.f32 "
        "{%0,%1,%2,%3}, {%4,%5,%6,%7}, {%8,%9}, {%0,%1,%2,%3};"
        : "+f"(d[0]), "+f"(d[1]), "+f"(d[2]), "+f"(d[3])
        : "r"(a0), "r"(a1), "r"(a2), "r"(a3), "r"(b0), "r"(b1));
}

__device__ __forceinline__ void ldsm4(uint32_t& r0, uint32_t& r1, uint32_t& r2, uint32_t& r3,
                                      uint32_t addr) {
    asm volatile("ldmatrix.sync.aligned.m8n8.x4.shared.b16 {%0,%1,%2,%3}, [%4];"
                 : "=r"(r0), "=r"(r1), "=r"(r2), "=r"(r3) : "r"(addr));
}

__device__ __forceinline__ void red2(float* p, float x, float y) {
    asm volatile("red.global.add.v2.f32 [%0], {%1, %2};"
                 :: "l"(p), "f"(x), "f"(y) : "memory");
}

// ---------------------------------------------------------------------------
// Core 128x128x128 tile: gather -> tf32 MMA (LDSM fragments) -> scatter.
// 256 threads (8 warps), warp owns 16 M-rows.
// As [128][132] tf32 (m,k)   Ws [128][132] tf32 = W^T (n,k). Stride 132 words
// makes both scalar stores and LDSM row-groups bank-conflict-free.
// ---------------------------------------------------------------------------
template <bool IDENTITY>
__device__ __forceinline__ void
tile_gemm(const float* __restrict__ A, const float* __restrict__ W,
          float* __restrict__ out,
          const int* __restrict__ u_idx, const int* __restrict__ v_idx,
          int tile0, uint32_t* As, uint32_t* Ws, int* su) {
    const int tid  = threadIdx.x;
    const int warp = tid >> 5, lane = tid & 31;

    // Stage W transposed (coalesced global reads, tf32-convert inbound)
    for (int i = tid; i < 4096; i += 256) {
        int n = i & 127, r = i >> 7;   // r in [0,32): k-groups of 4
#pragma unroll
        for (int j = 0; j < 4; j++) {
            int k = 4 * r + j;
            Ws[n * 132 + k] = f2tf(W[k * 128 + n]);
        }
    }
    // Gather A rows (16B loads; random rows mostly hit L2)
    for (int i = tid; i < 4096; i += 256) {
        int r = i >> 5, s = i & 31;
        int src = IDENTITY ? (tile0 + r) : v_idx[tile0 + r];
        float4 av = reinterpret_cast<const float4*>(A)[src * 32 + s];
        uint32_t* p = As + r * 132 + s * 4;
        p[0] = f2tf(av.x); p[1] = f2tf(av.y); p[2] = f2tf(av.z); p[3] = f2tf(av.w);
    }
    if (tid < 128) su[tid] = IDENTITY ? (tile0 + tid) : u_idx[tile0 + tid];
    __syncthreads();

    float acc[16][4];
#pragma unroll
    for (int nt = 0; nt < 16; nt++)
        acc[nt][0] = acc[nt][1] = acc[nt][2] = acc[nt][3] = 0.f;

    // LDSM per-lane addresses.
    // A x4: mat0 rows w*16+0..7 @k0 | mat1 rows +8 @k0 | mat2 rows +0..7 @k0+4 | mat3 +8 @k0+4
    const uint32_t As_u32 = (uint32_t)__cvta_generic_to_shared(As);
    const uint32_t Ws_u32 = (uint32_t)__cvta_generic_to_shared(Ws);
    const int a_row = warp * 16 + ((lane >> 3) & 1) * 8 + (lane & 7);
    const uint32_t a_addr = As_u32 + (a_row * 132 + (lane >> 4) * 4) * 4;
    // B x4 (per nt-pair): mat0 n-rows p16+0..7 @k0 | mat1 same @k0+4 | mat2 rows +8 @k0 | mat3 +8 @k0+4
    const int b_row = ((lane >> 4) & 1) * 8 + (lane & 7);
    const uint32_t b_addr = Ws_u32 + (b_row * 132 + ((lane >> 3) & 1) * 4) * 4;

#pragma unroll
    for (int k0 = 0; k0 < 128; k0 += 8) {
        uint32_t A0, A1, A2, A3;
        ldsm4(A0, A1, A2, A3, a_addr + k0 * 4);
#pragma unroll
        for (int p = 0; p < 8; p++) {
            uint32_t B0, B1, B2, B3;
            ldsm4(B0, B1, B2, B3, b_addr + (p * 16 * 132 + k0) * 4);
            mma8(acc[2 * p],     A0, A1, A2, A3, B0, B1);
            mma8(acc[2 * p + 1], A0, A1, A2, A3, B2, B3);
        }
    }

    const int g = lane >> 2, tg = lane & 3;
    const int r0 = warp * 16 + g, r1 = r0 + 8;
    const int d0 = su[r0], d1 = su[r1];
#pragma unroll
    for (int nt = 0; nt < 16; nt++) {
        int col = nt * 8 + 2 * tg;
        float* p0 = out + (size_t)d0 * 128 + col;
        float* p1 = out + (size_t)d1 * 128 + col;
        if (IDENTITY) {
            *reinterpret_cast<float2*>(p0) = make_float2(acc[nt][0], acc[nt][1]);
            *reinterpret_cast<float2*>(p1) = make_float2(acc[nt][2], acc[nt][3]);
        } else {
            red2(p0, acc[nt][0], acc[nt][1]);
            red2(p1, acc[nt][2], acc[nt][3]);
        }
    }
}

// Dense per-node GEMM (plain stores; doubles as zero-init of temp)
__global__ void __launch_bounds__(256, 1)
gemm_identity(const float* __restrict__ A, const float* __restrict__ W,
              float* __restrict__ out) {
    extern __shared__ uint32_t sm[];
    __shared__ int su[128];
    tile_gemm<true>(A, W, out, nullptr, nullptr, blockIdx.x * 128,
                    sm, sm + 128 * 132, su);
}

// One launch per residual block covering all 14 edge-scatter GEMMs:
// [0,6144) pre (6 scales x 1024 tiles), [6144,12288) suc,
// [12288,12544) left, [12544,12800) right.
__global__ void __launch_bounds__(256, 1)
edges_kernel(const float* __restrict__ A,
             const float* __restrict__ pre_w, const float* __restrict__ suc_w,
             const float* __restrict__ left_w, const float* __restrict__ right_w,
             const int* __restrict__ pre_u, const int* __restrict__ pre_v,
             const int* __restrict__ suc_u, const int* __restrict__ suc_v,
             const int* __restrict__ left_u, const int* __restrict__ left_v,
             const int* __restrict__ right_u, const int* __restrict__ right_v,
             float* __restrict__ out) {
    extern __shared__ uint32_t sm[];
    __shared__ int su[128];

    int cid = blockIdx.x;
    const float* W; const int *u, *v; int tile0;
    if (cid < 6144) {
        int s = cid >> 10;
        W = pre_w + s * 16384; u = pre_u + s * EE; v = pre_v + s * EE;
        tile0 = (cid & 1023) * 128;
    } else if (cid < 12288) {
        cid -= 6144; int s = cid >> 10;
        W = suc_w + s * 16384; u = suc_u + s * EE; v = suc_v + s * EE;
        tile0 = (cid & 1023) * 128;
    } else if (cid < 12544) {
        cid -= 12288;
        W = left_w; u = left_u; v = left_v; tile0 = cid * 128;
    } else {
        cid -= 12544;
        W = right_w; u = right_u; v = right_v; tile0 = cid * 128;
    }
    tile_gemm<false>(A, W, out, u, v, tile0, sm, sm + 128 * 132, su);
}

// ---------------------------------------------------------------------------
// GroupNorm(num_groups=1) over 128 channels, warp-per-row.
// MODE 0: GN   MODE 1: relu(GN)   MODE 2: relu(GN + res)
// ---------------------------------------------------------------------------
template <int MODE>
__global__ void __launch_bounds__(128)
gn_kernel(const float* __restrict__ in, const float* __restrict__ gamma,
          const float* __restrict__ beta, const float* __restrict__ res,
          float* __restrict__ out) {
    const int warp = threadIdx.x >> 5, lane = threadIdx.x & 31;
    const size_t row = (size_t)blockIdx.x * 4 + warp;
    float4 x = reinterpret_cast<const float4*>(in)[row * 32 + lane];
    float s = x.x + x.y + x.z + x.w;
    float q = x.x * x.x + x.y * x.y + x.z * x.z + x.w * x.w;
#pragma unroll
    for (int o = 16; o > 0; o >>= 1) {
        s += __shfl_xor_sync(0xffffffffu, s, o);
        q += __shfl_xor_sync(0xffffffffu, q, o);
    }
    float mu  = s * (1.f / 128.f);
    float var = q * (1.f / 128.f) - mu * mu;
    float inv = rsqrtf(var + 1e-5f);
    float4 gm = reinterpret_cast<const float4*>(gamma)[lane];
    float4 bt = reinterpret_cast<const float4*>(beta)[lane];
    float4 y;
    y.x = (x.x - mu) * inv * gm.x + bt.x;
    y.y = (x.y - mu) * inv * gm.y + bt.y;
    y.z = (x.z - mu) * inv * gm.z + bt.z;
    y.w = (x.w - mu) * inv * gm.w + bt.w;
    if (MODE == 2) {
        float4 rv = reinterpret_cast<const float4*>(res)[row * 32 + lane];
        y.x += rv.x; y.y += rv.y; y.z += rv.z; y.w += rv.w;
    }
    if (MODE >= 1) {
        y.x = fmaxf(y.x, 0.f); y.y = fmaxf(y.y, 0.f);
        y.z = fmaxf(y.z, 0.f); y.w = fmaxf(y.w, 0.f);
    }
    reinterpret_cast<float4*>(out)[row * 32 + lane] = y;
}

// ---------------------------------------------------------------------------
// h1 = relu(ctrs @ W0a + b0a), h2 = relu(feats @ W0b + b0b)   (K=2 matvec)
// ---------------------------------------------------------------------------
__global__ void __launch_bounds__(256)
mlp0_kernel(const float* __restrict__ ctrs, const float* __restrict__ feats,
            const float* __restrict__ w0a, const float* __restrict__ b0a,
            const float* __restrict__ w0b, const float* __restrict__ b0b,
            float* __restrict__ h1, float* __restrict__ h2) {
    const int idx = blockIdx.x * 256 + threadIdx.x;  // over N*32 float4 slots
    const int n = idx >> 5, s = idx & 31;
    float c0 = ctrs[n * 2], c1 = ctrs[n * 2 + 1];
    float e0 = feats[n * 2], e1 = feats[n * 2 + 1];

    float4 wa0 = reinterpret_cast<const float4*>(w0a)[s];
    float4 wa1 = reinterpret_cast<const float4*>(w0a)[32 + s];
    float4 ba  = reinterpret_cast<const float4*>(b0a)[s];
    float4 o1;
    o1.x = fmaxf(c0 * wa0.x + c1 * wa1.x + ba.x, 0.f);
    o1.y = fmaxf(c0 * wa0.y + c1 * wa1.y + ba.y, 0.f);
    o1.z = fmaxf(c0 * wa0.z + c1 * wa1.z + ba.z, 0.f);
    o1.w = fmaxf(c0 * wa0.w + c1 * wa1.w + ba.w, 0.f);
    reinterpret_cast<float4*>(h1)[idx] = o1;

    float4 wb0 = reinterpret_cast<const float4*>(w0b)[s];
    float4 wb1 = reinterpret_cast<const float4*>(w0b)[32 + s];
    float4 bb  = reinterpret_cast<const float4*>(b0b)[s];
    float4 o2;
    o2.x = fmaxf(e0 * wb0.x + e1 * wb1.x + bb.x, 0.f);
    o2.y = fmaxf(e0 * wb0.y + e1 * wb1.y + bb.y, 0.f);
    o2.z = fmaxf(e0 * wb0.z + e1 * wb1.z + bb.z, 0.f);
    o2.w = fmaxf(e0 * wb0.w + e1 * wb1.w + bb.w, 0.f);
    reinterpret_cast<float4*>(h2)[idx] = o2;
}

// ---------------------------------------------------------------------------

extern "C" void kernel_launch(void* const* d_in, const int* in_sizes, int n_in,
                              void* d_out, int out_size) {
    const float* ctrs   = (const float*)d_in[0];
    const float* feats  = (const float*)d_in[1];
    const int* pre_u    = (const int*)d_in[2];
    const int* pre_v    = (const int*)d_in[3];
    const int* suc_u    = (const int*)d_in[4];
    const int* suc_v    = (const int*)d_in[5];
    const int* left_u   = (const int*)d_in[6];
    const int* left_v   = (const int*)d_in[7];
    const int* right_u  = (const int*)d_in[8];
    const int* right_v  = (const int*)d_in[9];
    const float* ic_w0  = (const float*)d_in[10];
    const float* ic_b0  = (const float*)d_in[11];
    const float* ic_w1  = (const float*)d_in[12];
    const float* ic_g   = (const float*)d_in[13];
    const float* ic_bt  = (const float*)d_in[14];
    const float* if_w0  = (const float*)d_in[15];
    const float* if_b0  = (const float*)d_in[16];
    const float* if_w1  = (const float*)d_in[17];
    const float* if_g   = (const float*)d_in[18];
    const float* if_bt  = (const float*)d_in[19];
    const float* ctr_w  = (const float*)d_in[20];
    const float* pre_w  = (const float*)d_in[21];
    const float* suc_w  = (const float*)d_in[22];
    const float* left_w = (const float*)d_in[23];
    const float* right_w= (const float*)d_in[24];
    const float* norm_g = (const float*)d_in[25];
    const float* norm_b = (const float*)d_in[26];
    const float* ctr2_w = (const float*)d_in[27];
    const float* ctr2_g = (const float*)d_in[28];
    const float* ctr2_b = (const float*)d_in[29];

    float* feat = (float*)d_out;
    float *temp, *feat2, *h2;
    cudaGetSymbolAddress((void**)&temp,  g_temp);
    cudaGetSymbolAddress((void**)&feat2, g_feat2);
    cudaGetSymbolAddress((void**)&h2,    g_h2);

    constexpr int SMEMB = 2 * 128 * 132 * 4;  // 135168 bytes
    cudaFuncSetAttribute((const void*)gemm_identity,
                         cudaFuncAttributeMaxDynamicSharedMemorySize, SMEMB);
    cudaFuncSetAttribute((const void*)edges_kernel,
                         cudaFuncAttributeMaxDynamicSharedMemorySize, SMEMB);

    // ---- input MLPs: feat = relu(GN(h1@ic_w1) + GN(h2@if_w1)) ----
    mlp0_kernel<<<NN * 32 / 256, 256>>>(ctrs, feats, ic_w0, ic_b0, if_w0, if_b0,
                                        feat2, h2);
    gemm_identity<<<NN / 128, 256, SMEMB>>>(feat2, ic_w1, temp);
    gn_kernel<0><<<NN / 4, 128>>>(temp, ic_g, ic_bt, nullptr, feat2);   // f1 -> feat2
    gemm_identity<<<NN / 128, 256, SMEMB>>>(h2, if_w1, temp);
    gn_kernel<2><<<NN / 4, 128>>>(temp, if_g, if_bt, feat2, feat);      // feat = relu(f2+f1)

    // ---- 4 residual fusion blocks ----
    for (int i = 0; i < BBL; i++) {
        // temp = feat @ ctr_w[i]   (plain store: doubles as the zero-init)
        gemm_identity<<<NN / 128, 256, SMEMB>>>(feat, ctr_w + i * 16384, temp);
        // all 14 edge-scatter GEMMs in one launch
        edges_kernel<<<12800, 256, SMEMB>>>(
            feat,
            pre_w + i * SSC * 16384, suc_w + i * SSC * 16384,
            left_w + i * 16384, right_w + i * 16384,
            pre_u, pre_v, suc_u, suc_v, left_u, left_v, right_u, right_v,
            temp);

        // feat2 = relu(GN(temp))
        gn_kernel<1><<<NN / 4, 128>>>(temp, norm_g + i * 128, norm_b + i * 128,
                                      nullptr, feat2);
        // temp = feat2 @ ctr2_w[i]
        gemm_identity<<<NN / 128, 256, SMEMB>>>(feat2, ctr2_w + i * 16384, temp);
        // feat = relu(GN(temp) + feat)   (in-place residual, row-local)
        gn_kernel<2><<<NN / 4, 128>>>(temp, ctr2_g + i * 128, ctr2_b + i * 128,
                                      feat, feat);
    }
}

// round 5
// speedup vs baseline: 2.4164x; 2.2380x over previous
#include <cuda_runtime.h>
#include <cstdint>

#define NN   131072
#define SSC  6
#define BBL  4
#define EE   131072
#define ELL  32768
#define NT   8        // tiles per CTA

// Scratch buffers (device globals — no runtime allocation allowed)
__device__ float g_temp [NN * 128];
__device__ float g_feat2[NN * 128];
__device__ float g_h2   [NN * 128];

__device__ __forceinline__ uint32_t f2tf(float x) {
    uint32_t r;
    asm("cvt.rna.tf32.f32 %0, %1;" : "=r"(r) : "f"(x));
    return r;
}
__device__ __forceinline__ uint32_t r2tf(uint32_t x) {
    uint32_t r;
    asm("cvt.rna.tf32.f32 %0, %1;" : "=r"(r) : "f"(__uint_as_float(x)));
    return r;
}

__device__ __forceinline__ void mma8(float* d, uint32_t a0, uint32_t a1, uint32_t a2, uint32_t a3,
                                     uint32_t b0, uint32_t b1) {
    asm volatile(
        "mma.sync.aligned.m16n8k8.row.col.f32.tf32.tf32.f32 "
        "{%0,%1,%2,%3}, {%4,%5,%6,%7}, {%8,%9}, {%0,%1,%2,%3};"
        : "+f"(d[0]), "+f"(d[1]), "+f"(d[2]), "+f"(d[3])
        : "r"(a0), "r"(a1), "r"(a2), "r"(a3), "r"(b0), "r"(b1));
}

__device__ __forceinline__ void ldsm4(uint32_t& r0, uint32_t& r1, uint32_t& r2, uint32_t& r3,
                                      uint32_t addr) {
    asm volatile("ldmatrix.sync.aligned.m8n8.x4.shared.b16 {%0,%1,%2,%3}, [%4];"
                 : "=r"(r0), "=r"(r1), "=r"(r2), "=r"(r3) : "r"(addr));
}

__device__ __forceinline__ void red2(float* p, float x, float y) {
    asm volatile("red.global.add.v2.f32 [%0], {%1, %2};"
                 :: "l"(p), "f"(x), "f"(y) : "memory");
}

__device__ __forceinline__ void cpa16(uint32_t dst, const void* src) {
    asm volatile("cp.async.ca.shared.global [%0], [%1], 16;" :: "r"(dst), "l"(src));
}
__device__ __forceinline__ void cpcommit() {
    asm volatile("cp.async.commit_group;" ::: "memory");
}
template <int N> __device__ __forceinline__ void cpwait() {
    asm volatile("cp.async.wait_group %0;" :: "n"(N) : "memory");
}

// ---------------------------------------------------------------------------
// Persistent-chunk tile loop: one CTA handles NT consecutive 128-edge tiles
// sharing one W. W staged (tf32-transposed) ONCE; A gathers double-buffered
// via cp.async (raw fp32 in smem, tf32-convert on fragment registers).
// Smem: Ws[128][132] | As0[128][132] | As1[128][132]  (202752 B dynamic)
// ---------------------------------------------------------------------------
template <bool IDENTITY>
__device__ __forceinline__ void
tile_loop(const float* __restrict__ A, const float* __restrict__ W,
          float* __restrict__ out,
          const int* __restrict__ u_idx, const int* __restrict__ v_idx,
          int edge0) {
    extern __shared__ uint32_t sm[];
    uint32_t* Ws  = sm;                       // [128][132] tf32 W^T
    uint32_t* As0 = sm + 128 * 132;           // [128][132] raw fp32
    uint32_t* As1 = As0 + 128 * 132;
    __shared__ int vbuf[NT * 128];
    __shared__ int ubuf[NT * 128];

    const int tid  = threadIdx.x;
    const int warp = tid >> 5, lane = tid & 31;

    const uint32_t Ws_u32  = (uint32_t)__cvta_generic_to_shared(Ws);
    const uint32_t As0_u32 = (uint32_t)__cvta_generic_to_shared(As0);
    const uint32_t As1_u32 = (uint32_t)__cvta_generic_to_shared(As1);

    // Prefetch all NT tiles' u/v indices (1024 ints each) to smem.
    if (!IDENTITY) {
        uint32_t vb = (uint32_t)__cvta_generic_to_shared(vbuf);
        uint32_t ub = (uint32_t)__cvta_generic_to_shared(ubuf);
        cpa16(vb + tid * 16, v_idx + edge0 + tid * 4);
        cpa16(ub + tid * 16, u_idx + edge0 + tid * 4);
        cpcommit();
        cpwait<0>();
        __syncthreads();
    }

    // Issue one tile's 64KB A-gather as cp.async (16 rows x 16B per thread).
    auto issue = [&](int t, uint32_t dstbase) {
#pragma unroll
        for (int j = 0; j < 16; j++) {
            int r = (tid >> 5) + 8 * j;
            int src = IDENTITY ? (edge0 + t * 128 + r) : vbuf[t * 128 + r];
            cpa16(dstbase + (uint32_t)(r * 132 + lane * 4) * 4,
                  A + (size_t)src * 128 + lane * 4);
        }
        cpcommit();
    };
    issue(0, As0_u32);

    // Stage W transposed+tf32 once (overlaps tile0 gather arrival).
    for (int i = tid; i < 4096; i += 256) {
        int n = i & 127, r = i >> 7;
#pragma unroll
        for (int j = 0; j < 4; j++) {
            int k = 4 * r + j;
            Ws[n * 132 + k] = f2tf(W[k * 128 + n]);
        }
    }

    // LDSM per-lane address components (see R3 derivation).
    const int a_row = warp * 16 + ((lane >> 3) & 1) * 8 + (lane & 7);
    const uint32_t a_off = (uint32_t)(a_row * 132 + (lane >> 4) * 4) * 4;
    const int b_row = ((lane >> 4) & 1) * 8 + (lane & 7);
    const uint32_t b_addr = Ws_u32 + (uint32_t)(b_row * 132 + ((lane >> 3) & 1) * 4) * 4;
    const int g = lane >> 2, tg = lane & 3;

    for (int t = 0; t < NT; t++) {
        if (t + 1 < NT) {
            issue(t + 1, (t & 1) ? As0_u32 : As1_u32);
            cpwait<1>();                       // tile t's group complete
        } else {
            cpwait<0>();
        }
        __syncthreads();                       // smem data + W visible

        const uint32_t a_base = ((t & 1) ? As1_u32 : As0_u32) + a_off;

        float acc[16][4];
#pragma unroll
        for (int nt = 0; nt < 16; nt++)
            acc[nt][0] = acc[nt][1] = acc[nt][2] = acc[nt][3] = 0.f;

#pragma unroll
        for (int k0 = 0; k0 < 128; k0 += 8) {
            uint32_t A0, A1, A2, A3;
            ldsm4(A0, A1, A2, A3, a_base + k0 * 4);
            A0 = r2tf(A0); A1 = r2tf(A1); A2 = r2tf(A2); A3 = r2tf(A3);
#pragma unroll
            for (int p = 0; p < 8; p++) {
                uint32_t B0, B1, B2, B3;
                ldsm4(B0, B1, B2, B3, b_addr + (uint32_t)(p * 16 * 132 + k0) * 4);
                mma8(acc[2 * p],     A0, A1, A2, A3, B0, B1);
                mma8(acc[2 * p + 1], A0, A1, A2, A3, B2, B3);
            }
        }

        const int r0 = warp * 16 + g, r1 = r0 + 8;
        const int d0 = IDENTITY ? (edge0 + t * 128 + r0) : ubuf[t * 128 + r0];
        const int d1 = IDENTITY ? (edge0 + t * 128 + r1) : ubuf[t * 128 + r1];
#pragma unroll
        for (int nt = 0; nt < 16; nt++) {
            int col = nt * 8 + 2 * tg;
            float* p0 = out + (size_t)d0 * 128 + col;
            float* p1 = out + (size_t)d1 * 128 + col;
            if (IDENTITY) {
                *reinterpret_cast<float2*>(p0) = make_float2(acc[nt][0], acc[nt][1]);
                *reinterpret_cast<float2*>(p1) = make_float2(acc[nt][2], acc[nt][3]);
            } else {
                red2(p0, acc[nt][0], acc[nt][1]);
                red2(p1, acc[nt][2], acc[nt][3]);
            }
        }
        __syncthreads();   // all reads of this A-buffer done before reuse
    }
}

// Dense per-node GEMM: 128 CTAs x NT tiles (plain stores; zero-inits temp)
__global__ void __launch_bounds__(256, 1)
gemm_identity(const float* __restrict__ A, const float* __restrict__ W,
              float* __restrict__ out) {
    tile_loop<true>(A, W, out, nullptr, nullptr, blockIdx.x * (NT * 128));
}

// All 14 edge-scatter GEMMs of one residual block in one launch.
// CTA map: [0,768) pre (6 seg x 128 chunks), [768,1536) suc,
//          [1536,1568) left, [1568,1600) right. Chunk = NT*128 = 1024 edges.
__global__ void __launch_bounds__(256, 1)
edges_kernel(const float* __restrict__ A,
             const float* __restrict__ pre_w, const float* __restrict__ suc_w,
             const float* __restrict__ left_w, const float* __restrict__ right_w,
             const int* __restrict__ pre_u, const int* __restrict__ pre_v,
             const int* __restrict__ suc_u, const int* __restrict__ suc_v,
             const int* __restrict__ left_u, const int* __restrict__ left_v,
             const int* __restrict__ right_u, const int* __restrict__ right_v,
             float* __restrict__ out) {
    int cid = blockIdx.x;
    const float* W; const int *u, *v; int base;
    if (cid < 768) {
        int s = cid >> 7;
        W = pre_w + s * 16384; u = pre_u + s * EE; v = pre_v + s * EE;
        base = (cid & 127) * 1024;
    } else if (cid < 1536) {
        cid -= 768; int s = cid >> 7;
        W = suc_w + s * 16384; u = suc_u + s * EE; v = suc_v + s * EE;
        base = (cid & 127) * 1024;
    } else if (cid < 1568) {
        W = left_w; u = left_u; v = left_v; base = (cid - 1536) * 1024;
    } else {
        W = right_w; u = right_u; v = right_v; base = (cid - 1568) * 1024;
    }
    tile_loop<false>(A, W, out, u, v, base);
}

// ---------------------------------------------------------------------------
// GroupNorm(num_groups=1) over 128 channels, warp-per-row.
// MODE 0: GN   MODE 1: relu(GN)   MODE 2: relu(GN + res)
// ---------------------------------------------------------------------------
template <int MODE>
__global__ void __launch_bounds__(128)
gn_kernel(const float* __restrict__ in, const float* __restrict__ gamma,
          const float* __restrict__ beta, const float* __restrict__ res,
          float* __restrict__ out) {
    const int warp = threadIdx.x >> 5, lane = threadIdx.x & 31;
    const size_t row = (size_t)blockIdx.x * 4 + warp;
    float4 x = reinterpret_cast<const float4*>(in)[row * 32 + lane];
    float s = x.x + x.y + x.z + x.w;
    float q = x.x * x.x + x.y * x.y + x.z * x.z + x.w * x.w;
#pragma unroll
    for (int o = 16; o > 0; o >>= 1) {
        s += __shfl_xor_sync(0xffffffffu, s, o);
        q += __shfl_xor_sync(0xffffffffu, q, o);
    }
    float mu  = s * (1.f / 128.f);
    float var = q * (1.f / 128.f) - mu * mu;
    float inv = rsqrtf(var + 1e-5f);
    float4 gm = reinterpret_cast<const float4*>(gamma)[lane];
    float4 bt = reinterpret_cast<const float4*>(beta)[lane];
    float4 y;
    y.x = (x.x - mu) * inv * gm.x + bt.x;
    y.y = (x.y - mu) * inv * gm.y + bt.y;
    y.z = (x.z - mu) * inv * gm.z + bt.z;
    y.w = (x.w - mu) * inv * gm.w + bt.w;
    if (MODE == 2) {
        float4 rv = reinterpret_cast<const float4*>(res)[row * 32 + lane];
        y.x += rv.x; y.y += rv.y; y.z += rv.z; y.w += rv.w;
    }
    if (MODE >= 1) {
        y.x = fmaxf(y.x, 0.f); y.y = fmaxf(y.y, 0.f);
        y.z = fmaxf(y.z, 0.f); y.w = fmaxf(y.w, 0.f);
    }
    reinterpret_cast<float4*>(out)[row * 32 + lane] = y;
}

// ---------------------------------------------------------------------------
// h1 = relu(ctrs @ W0a + b0a), h2 = relu(feats @ W0b + b0b)   (K=2 matvec)
// ---------------------------------------------------------------------------
__global__ void __launch_bounds__(256)
mlp0_kernel(const float* __restrict__ ctrs, const float* __restrict__ feats,
            const float* __restrict__ w0a, const float* __restrict__ b0a,
            const float* __restrict__ w0b, const float* __restrict__ b0b,
            float* __restrict__ h1, float* __restrict__ h2) {
    const int idx = blockIdx.x * 256 + threadIdx.x;  // over N*32 float4 slots
    const int n = idx >> 5, s = idx & 31;
    float c0 = ctrs[n * 2], c1 = ctrs[n * 2 + 1];
    float e0 = feats[n * 2], e1 = feats[n * 2 + 1];

    float4 wa0 = reinterpret_cast<const float4*>(w0a)[s];
    float4 wa1 = reinterpret_cast<const float4*>(w0a)[32 + s];
    float4 ba  = reinterpret_cast<const float4*>(b0a)[s];
    float4 o1;
    o1.x = fmaxf(c0 * wa0.x + c1 * wa1.x + ba.x, 0.f);
    o1.y = fmaxf(c0 * wa0.y + c1 * wa1.y + ba.y, 0.f);
    o1.z = fmaxf(c0 * wa0.z + c1 * wa1.z + ba.z, 0.f);
    o1.w = fmaxf(c0 * wa0.w + c1 * wa1.w + ba.w, 0.f);
    reinterpret_cast<float4*>(h1)[idx] = o1;

    float4 wb0 = reinterpret_cast<const float4*>(w0b)[s];
    float4 wb1 = reinterpret_cast<const float4*>(w0b)[32 + s];
    float4 bb  = reinterpret_cast<const float4*>(b0b)[s];
    float4 o2;
    o2.x = fmaxf(e0 * wb0.x + e1 * wb1.x + bb.x, 0.f);
    o2.y = fmaxf(e0 * wb0.y + e1 * wb1.y + bb.y, 0.f);
    o2.z = fmaxf(e0 * wb0.z + e1 * wb1.z + bb.z, 0.f);
    o2.w = fmaxf(e0 * wb0.w + e1 * wb1.w + bb.w, 0.f);
    reinterpret_cast<float4*>(h2)[idx] = o2;
}

// ---------------------------------------------------------------------------

extern "C" void kernel_launch(void* const* d_in, const int* in_sizes, int n_in,
                              void* d_out, int out_size) {
    const float* ctrs   = (const float*)d_in[0];
    const float* feats  = (const float*)d_in[1];
    const int* pre_u    = (const int*)d_in[2];
    const int* pre_v    = (const int*)d_in[3];
    const int* suc_u    = (const int*)d_in[4];
    const int* suc_v    = (const int*)d_in[5];
    const int* left_u   = (const int*)d_in[6];
    const int* left_v   = (const int*)d_in[7];
    const int* right_u  = (const int*)d_in[8];
    const int* right_v  = (const int*)d_in[9];
    const float* ic_w0  = (const float*)d_in[10];
    const float* ic_b0  = (const float*)d_in[11];
    const float* ic_w1  = (const float*)d_in[12];
    const float* ic_g   = (const float*)d_in[13];
    const float* ic_bt  = (const float*)d_in[14];
    const float* if_w0  = (const float*)d_in[15];
    const float* if_b0  = (const float*)d_in[16];
    const float* if_w1  = (const float*)d_in[17];
    const float* if_g   = (const float*)d_in[18];
    const float* if_bt  = (const float*)d_in[19];
    const float* ctr_w  = (const float*)d_in[20];
    const float* pre_w  = (const float*)d_in[21];
    const float* suc_w  = (const float*)d_in[22];
    const float* left_w = (const float*)d_in[23];
    const float* right_w= (const float*)d_in[24];
    const float* norm_g = (const float*)d_in[25];
    const float* norm_b = (const float*)d_in[26];
    const float* ctr2_w = (const float*)d_in[27];
    const float* ctr2_g = (const float*)d_in[28];
    const float* ctr2_b = (const float*)d_in[29];

    float* feat = (float*)d_out;
    float *temp, *feat2, *h2;
    cudaGetSymbolAddress((void**)&temp,  g_temp);
    cudaGetSymbolAddress((void**)&feat2, g_feat2);
    cudaGetSymbolAddress((void**)&h2,    g_h2);

    constexpr int SMEMB = 3 * 128 * 132 * 4;  // 202752 bytes
    cudaFuncSetAttribute((const void*)gemm_identity,
                         cudaFuncAttributeMaxDynamicSharedMemorySize, SMEMB);
    cudaFuncSetAttribute((const void*)edges_kernel,
                         cudaFuncAttributeMaxDynamicSharedMemorySize, SMEMB);

    constexpr int GID = NN / (NT * 128);   // 128 CTAs for dense GEMMs

    // ---- input MLPs: feat = relu(GN(h1@ic_w1) + GN(h2@if_w1)) ----
    mlp0_kernel<<<NN * 32 / 256, 256>>>(ctrs, feats, ic_w0, ic_b0, if_w0, if_b0,
                                        feat2, h2);
    gemm_identity<<<GID, 256, SMEMB>>>(feat2, ic_w1, temp);
    gn_kernel<0><<<NN / 4, 128>>>(temp, ic_g, ic_bt, nullptr, feat2);   // f1 -> feat2
    gemm_identity<<<GID, 256, SMEMB>>>(h2, if_w1, temp);
    gn_kernel<2><<<NN / 4, 128>>>(temp, if_g, if_bt, feat2, feat);      // feat = relu(f2+f1)

    // ---- 4 residual fusion blocks ----
    for (int i = 0; i < BBL; i++) {
        // temp = feat @ ctr_w[i]   (plain store: doubles as the zero-init)
        gemm_identity<<<GID, 256, SMEMB>>>(feat, ctr_w + i * 16384, temp);
        // all 14 edge-scatter GEMMs in one launch
        edges_kernel<<<1600, 256, SMEMB>>>(
            feat,
            pre_w + i * SSC * 16384, suc_w + i * SSC * 16384,
            left_w + i * 16384, right_w + i * 16384,
            pre_u, pre_v, suc_u, suc_v, left_u, left_v, right_u, right_v,
            temp);

        // feat2 = relu(GN(temp))
        gn_kernel<1><<<NN / 4, 128>>>(temp, norm_g + i * 128, norm_b + i * 128,
                                      nullptr, feat2);
        // temp = feat2 @ ctr2_w[i]
        gemm_identity<<<GID, 256, SMEMB>>>(feat2, ctr2_w + i * 16384, temp);
        // feat = relu(GN(temp) + feat)   (in-place residual, row-local)
        gn_kernel<2><<<NN / 4, 128>>>(temp, ctr2_g + i * 128, ctr2_b + i * 128,
                                      feat, feat);
    }
}

// round 11
// speedup vs baseline: 3.7403x; 1.5479x over previous
#include <cuda_runtime.h>
#include <cuda_fp16.h>
#include <cstdint>

#define NN   131072
#define SSC  6
#define BBL  4
#define EE   131072
#define ELL  32768

// Scratch (device globals — no runtime allocation allowed)
__device__ float  g_temp [NN * 128];
__device__ float  g_f1   [NN * 128];
__device__ __half g_featH[NN * 128];
__device__ __half g_aH   [NN * 128];
__device__ __half g_bH   [NN * 128];

__device__ __forceinline__ void mma16(float* d, uint32_t a0, uint32_t a1, uint32_t a2, uint32_t a3,
                                      uint32_t b0, uint32_t b1) {
    asm volatile(
        "mma.sync.aligned.m16n8k16.row.col.f32.f16.f16.f32 "
        "{%0,%1,%2,%3}, {%4,%5,%6,%7}, {%8,%9}, {%0,%1,%2,%3};"
        : "+f"(d[0]), "+f"(d[1]), "+f"(d[2]), "+f"(d[3])
        : "r"(a0), "r"(a1), "r"(a2), "r"(a3), "r"(b0), "r"(b1));
}

__device__ __forceinline__ void ldsm4(uint32_t& r0, uint32_t& r1, uint32_t& r2, uint32_t& r3,
                                      uint32_t addr) {
    asm volatile("ldmatrix.sync.aligned.m8n8.x4.shared.b16 {%0,%1,%2,%3}, [%4];"
                 : "=r"(r0), "=r"(r1), "=r"(r2), "=r"(r3) : "r"(addr));
}

__device__ __forceinline__ void red4(float* p, float x, float y, float z, float w) {
    asm volatile("red.global.add.v4.f32 [%0], {%1, %2, %3, %4};"
                 :: "l"(p), "f"(x), "f"(y), "f"(z), "f"(w) : "memory");
}

__device__ __forceinline__ void cpa16(uint32_t dst, const void* src) {
    asm volatile("cp.async.ca.shared.global [%0], [%1], 16;" :: "r"(dst), "l"(src));
}
__device__ __forceinline__ void cpcommit() {
    asm volatile("cp.async.commit_group;" ::: "memory");
}
template <int N> __device__ __forceinline__ void cpwait() {
    asm volatile("cp.async.wait_group %0;" :: "n"(N) : "memory");
}

__device__ __forceinline__ uint2 pack4h(float a, float b, float c, float d) {
    __half2 lo = __floats2half2_rn(a, b), hi = __floats2half2_rn(c, d);
    uint2 r;
    r.x = *reinterpret_cast<uint32_t*>(&lo);
    r.y = *reinterpret_cast<uint32_t*>(&hi);
    return r;
}

// ---------------------------------------------------------------------------
// Tile loop: NTT consecutive 128-row tiles sharing one W (fp16 operands,
// fp32 accum). W staged once; A gathers double-buffered via cp.async.
// Smem layout (bytes): Ws[128][136]h @0 | As0 @34816 | As1 @69632 |
//                      vbuf @104448 | ubuf @108544.  Total 112640 -> 2 CTA/SM.
// Row pitch 272B (=17x16B) => ldmatrix 8-row fetches are conflict-free.
// ---------------------------------------------------------------------------
template <bool IDENTITY, int NTT>
__device__ __forceinline__ void
tile_loop(const __half* __restrict__ A, const float* __restrict__ W,
          float* __restrict__ out,
          const int* __restrict__ u_idx, const int* __restrict__ v_idx,
          int edge0) {
    extern __shared__ char sm[];
    __half* Ws  = reinterpret_cast<__half*>(sm);     // [128][136]
    int* vbuf = reinterpret_cast<int*>(sm + 104448);
    int* ubuf = reinterpret_cast<int*>(sm + 108544);

    const int tid = threadIdx.x, warp = tid >> 5, lane = tid & 31;
    const uint32_t Ws_u  = (uint32_t)__cvta_generic_to_shared(Ws);
    const uint32_t As0_u = Ws_u + 34816;
    const uint32_t As1_u = Ws_u + 69632;

    // Prefetch all NTT tiles' u/v indices.
    if (!IDENTITY) {
        const uint32_t vb = Ws_u + 104448, ub = Ws_u + 108544;
        for (int off = tid * 16; off < NTT * 128 * 4; off += 256 * 16) {
            cpa16(vb + off, reinterpret_cast<const char*>(v_idx + edge0) + off);
            cpa16(ub + off, reinterpret_cast<const char*>(u_idx + edge0) + off);
        }
        cpcommit();
        cpwait<0>();
        __syncthreads();
    }

    // One tile's 32KB fp16 gather: 2048 x 16B, 8 per thread, row-coalesced.
    auto issue = [&](int t, uint32_t dst) {
#pragma unroll
        for (int j = 0; j < 8; j++) {
            int o = tid + 256 * j;
            int row = o >> 4, seg = o & 15;
            int src = IDENTITY ? (edge0 + t * 128 + row) : vbuf[t * 128 + row];
            cpa16(dst + (uint32_t)(row * 272 + seg * 16),
                  reinterpret_cast<const char*>(A + (size_t)src * 128) + seg * 16);
        }
        cpcommit();
    };
    issue(0, As0_u);

    // Stage W^T fp16 once (overlaps tile0 gather).
    for (int i = tid; i < 4096; i += 256) {
        int n = i & 127, kq = i >> 7;
#pragma unroll
        for (int j = 0; j < 4; j++) {
            int k = kq * 4 + j;
            Ws[n * 136 + k] = __float2half_rn(W[k * 128 + n]);
        }
    }

    // ldmatrix lane addressing (b16, x4):
    // A: m0 rows w16+0..7 @k0 | m1 +8 @k0 | m2 rows @k0+8 | m3 +8 @k0+8
    const int a_row = warp * 16 + (lane & 7) + ((lane >> 3) & 1) * 8;
    const uint32_t a_off = (uint32_t)(a_row * 272 + ((lane >> 4) & 1) * 16);
    // B: m0 n p16+0..7 @k0 | m1 same @k0+8 | m2 +8 @k0 | m3 +8 @k0+8
    const int b_row = (lane & 7) + ((lane >> 4) & 1) * 8;
    const uint32_t b_base = Ws_u + (uint32_t)(b_row * 272 + ((lane >> 3) & 1) * 16);
    const int g = lane >> 2, tg = lane & 3;
    const bool lead = (tg & 1) == 0;

    for (int t = 0; t < NTT; t++) {
        if (t + 1 < NTT) {
            issue(t + 1, (t & 1) ? As0_u : As1_u);
            cpwait<1>();
        } else {
            cpwait<0>();
        }
        __syncthreads();

        const uint32_t a_base = ((t & 1) ? As1_u : As0_u) + a_off;

        float acc[16][4];
#pragma unroll
        for (int nt = 0; nt < 16; nt++)
            acc[nt][0] = acc[nt][1] = acc[nt][2] = acc[nt][3] = 0.f;

#pragma unroll
        for (int k0 = 0; k0 < 8; k0++) {   // 16 halves (32B) per step
            uint32_t A0, A1, A2, A3;
            ldsm4(A0, A1, A2, A3, a_base + k0 * 32);
#pragma unroll
            for (int p = 0; p < 8; p++) {
                uint32_t B0, B1, B2, B3;
                ldsm4(B0, B1, B2, B3, b_base + (uint32_t)(p * 4352 + k0 * 32));
                mma16(acc[2 * p],     A0, A1, A2, A3, B0, B1);
                mma16(acc[2 * p + 1], A0, A1, A2, A3, B2, B3);
            }
        }

        const int r0 = warp * 16 + g, r1 = r0 + 8;
        const int d0 = IDENTITY ? (edge0 + t * 128 + r0) : ubuf[t * 128 + r0];
        const int d1 = IDENTITY ? (edge0 + t * 128 + r1) : ubuf[t * 128 + r1];
#pragma unroll
        for (int nt = 0; nt < 16; nt++) {
            float x0 = acc[nt][0], x1 = acc[nt][1], x2 = acc[nt][2], x3 = acc[nt][3];
            float y0 = __shfl_xor_sync(0xffffffffu, x0, 1);
            float y1 = __shfl_xor_sync(0xffffffffu, x1, 1);
            float y2 = __shfl_xor_sync(0xffffffffu, x2, 1);
            float y3 = __shfl_xor_sync(0xffffffffu, x3, 1);
            if (lead) {   // even tg owns cols 2tg..2tg+3 (16B aligned)
                int col = nt * 8 + 2 * tg;
                float* p0 = out + (size_t)d0 * 128 + col;
                float* p1 = out + (size_t)d1 * 128 + col;
                if (IDENTITY) {
                    *reinterpret_cast<float4*>(p0) = make_float4(x0, x1, y0, y1);
                    *reinterpret_cast<float4*>(p1) = make_float4(x2, x3, y2, y3);
                } else {
                    red4(p0, x0, x1, y0, y1);
                    red4(p1, x2, x3, y2, y3);
                }
            }
        }
        __syncthreads();
    }
}

// Dense per-node GEMM: 256 CTAs x 4 tiles (plain stores; zero-inits temp)
__global__ void __launch_bounds__(256, 2)
gemm_identity(const __half* __restrict__ A, const float* __restrict__ W,
              float* __restrict__ out) {
    tile_loop<true, 4>(A, W, out, nullptr, nullptr, blockIdx.x * 512);
}

// All 14 edge-scatter GEMMs of one block. Chunk = 8*128 = 1024 edges.
// CTA map: [0,768) pre | [768,1536) suc | [1536,1568) left | [1568,1600) right
__global__ void __launch_bounds__(256, 2)
edges_kernel(const __half* __restrict__ A,
             const float* __restrict__ pre_w, const float* __restrict__ suc_w,
             const float* __restrict__ left_w, const float* __restrict__ right_w,
             const int* __restrict__ pre_u, const int* __restrict__ pre_v,
             const int* __restrict__ suc_u, const int* __restrict__ suc_v,
             const int* __restrict__ left_u, const int* __restrict__ left_v,
             const int* __restrict__ right_u, const int* __restrict__ right_v,
             float* __restrict__ out) {
    int cid = blockIdx.x;
    const float* W; const int *u, *v; int base;
    if (cid < 768) {
        int s = cid >> 7;
        W = pre_w + s * 16384; u = pre_u + s * EE; v = pre_v + s * EE;
        base = (cid & 127) * 1024;
    } else if (cid < 1536) {
        cid -= 768; int s = cid >> 7;
        W = suc_w + s * 16384; u = suc_u + s * EE; v = suc_v + s * EE;
        base = (cid & 127) * 1024;
    } else if (cid < 1568) {
        W = left_w; u = left_u; v = left_v; base = (cid - 1536) * 1024;
    } else {
        W = right_w; u = right_u; v = right_v; base = (cid - 1568) * 1024;
    }
    tile_loop<false, 8>(A, W, out, u, v, base);
}

// ---------------------------------------------------------------------------
// GroupNorm over 128 ch, warp-per-row.
// MODE 0: GN -> fp32.  MODE 1: relu(GN) -> fp16.  MODE 2: relu(GN+res) -> both.
// ---------------------------------------------------------------------------
template <int MODE>
__global__ void __launch_bounds__(128)
gn_kernel(const float* __restrict__ in, const float* __restrict__ gamma,
          const float* __restrict__ beta, const float* __restrict__ res,
          float* __restrict__ outF, __half* __restrict__ outH) {
    const int warp = threadIdx.x >> 5, lane = threadIdx.x & 31;
    const size_t row = (size_t)blockIdx.x * 4 + warp;
    float4 x = reinterpret_cast<const float4*>(in)[row * 32 + lane];
    float s = x.x + x.y + x.z + x.w;
    float q = x.x * x.x + x.y * x.y + x.z * x.z + x.w * x.w;
#pragma unroll
    for (int o = 16; o > 0; o >>= 1) {
        s += __shfl_xor_sync(0xffffffffu, s, o);
        q += __shfl_xor_sync(0xffffffffu, q, o);
    }
    float mu  = s * (1.f / 128.f);
    float var = q * (1.f / 128.f) - mu * mu;
    float inv = rsqrtf(var + 1e-5f);
    float4 gm = reinterpret_cast<const float4*>(gamma)[lane];
    float4 bt = reinterpret_cast<const float4*>(beta)[lane];
    float4 y;
    y.x = (x.x - mu) * inv * gm.x + bt.x;
    y.y = (x.y - mu) * inv * gm.y + bt.y;
    y.z = (x.z - mu) * inv * gm.z + bt.z;
    y.w = (x.w - mu) * inv * gm.w + bt.w;
    if (MODE == 2) {
        float4 rv = reinterpret_cast<const float4*>(res)[row * 32 + lane];
        y.x += rv.x; y.y += rv.y; y.z += rv.z; y.w += rv.w;
    }
    if (MODE >= 1) {
        y.x = fmaxf(y.x, 0.f); y.y = fmaxf(y.y, 0.f);
        y.z = fmaxf(y.z, 0.f); y.w = fmaxf(y.w, 0.f);
    }
    if (MODE != 1)
        reinterpret_cast<float4*>(outF)[row * 32 + lane] = y;
    if (MODE >= 1)
        reinterpret_cast<uint2*>(outH)[row * 32 + lane] = pack4h(y.x, y.y, y.z, y.w);
}

// ---------------------------------------------------------------------------
// h1 = relu(ctrs @ W0a + b0a), h2 = relu(feats @ W0b + b0b)  -> fp16 outputs
// ---------------------------------------------------------------------------
__global__ void __launch_bounds__(256)
mlp0_kernel(const float* __restrict__ ctrs, const float* __restrict__ feats,
            const float* __restrict__ w0a, const float* __restrict__ b0a,
            const float* __restrict__ w0b, const float* __restrict__ b0b,
            __half* __restrict__ h1, __half* __restrict__ h2) {
    const int idx = blockIdx.x * 256 + threadIdx.x;  // over N*32 4-elem slots
    const int n = idx >> 5, s = idx & 31;
    float c0 = ctrs[n * 2], c1 = ctrs[n * 2 + 1];
    float e0 = feats[n * 2], e1 = feats[n * 2 + 1];

    float4 wa0 = reinterpret_cast<const float4*>(w0a)[s];
    float4 wa1 = reinterpret_cast<const float4*>(w0a)[32 + s];
    float4 ba  = reinterpret_cast<const float4*>(b0a)[s];
    reinterpret_cast<uint2*>(h1)[idx] = pack4h(
        fmaxf(c0 * wa0.x + c1 * wa1.x + ba.x, 0.f),
        fmaxf(c0 * wa0.y + c1 * wa1.y + ba.y, 0.f),
        fmaxf(c0 * wa0.z + c1 * wa1.z + ba.z, 0.f),
        fmaxf(c0 * wa0.w + c1 * wa1.w + ba.w, 0.f));

    float4 wb0 = reinterpret_cast<const float4*>(w0b)[s];
    float4 wb1 = reinterpret_cast<const float4*>(w0b)[32 + s];
    float4 bb  = reinterpret_cast<const float4*>(b0b)[s];
    reinterpret_cast<uint2*>(h2)[idx] = pack4h(
        fmaxf(e0 * wb0.x + e1 * wb1.x + bb.x, 0.f),
        fmaxf(e0 * wb0.y + e1 * wb1.y + bb.y, 0.f),
        fmaxf(e0 * wb0.z + e1 * wb1.z + bb.z, 0.f),
        fmaxf(e0 * wb0.w + e1 * wb1.w + bb.w, 0.f));
}

// ---------------------------------------------------------------------------

extern "C" void kernel_launch(void* const* d_in, const int* in_sizes, int n_in,
                              void* d_out, int out_size) {
    const float* ctrs   = (const float*)d_in[0];
    const float* feats  = (const float*)d_in[1];
    const int* pre_u    = (const int*)d_in[2];
    const int* pre_v    = (const int*)d_in[3];
    const int* suc_u    = (const int*)d_in[4];
    const int* suc_v    = (const int*)d_in[5];
    const int* left_u   = (const int*)d_in[6];
    const int* left_v   = (const int*)d_in[7];
    const int* right_u  = (const int*)d_in[8];
    const int* right_v  = (const int*)d_in[9];
    const float* ic_w0  = (const float*)d_in[10];
    const float* ic_b0  = (const float*)d_in[11];
    const float* ic_w1  = (const float*)d_in[12];
    const float* ic_g   = (const float*)d_in[13];
    const float* ic_bt  = (const float*)d_in[14];
    const float* if_w0  = (const float*)d_in[15];
    const float* if_b0  = (const float*)d_in[16];
    const float* if_w1  = (const float*)d_in[17];
    const float* if_g   = (const float*)d_in[18];
    const float* if_bt  = (const float*)d_in[19];
    const float* ctr_w  = (const float*)d_in[20];
    const float* pre_w  = (const float*)d_in[21];
    const float* suc_w  = (const float*)d_in[22];
    const float* left_w = (const float*)d_in[23];
    const float* right_w= (const float*)d_in[24];
    const float* norm_g = (const float*)d_in[25];
    const float* norm_b = (const float*)d_in[26];
    const float* ctr2_w = (const float*)d_in[27];
    const float* ctr2_g = (const float*)d_in[28];
    const float* ctr2_b = (const float*)d_in[29];

    float* feat = (float*)d_out;
    float *temp, *f1;
    __half *featH, *aH, *bH;
    cudaGetSymbolAddress((void**)&temp,  g_temp);
    cudaGetSymbolAddress((void**)&f1,    g_f1);
    cudaGetSymbolAddress((void**)&featH, g_featH);
    cudaGetSymbolAddress((void**)&aH,    g_aH);
    cudaGetSymbolAddress((void**)&bH,    g_bH);

    constexpr int SMEMB = 112640;
    cudaFuncSetAttribute((const void*)gemm_identity,
                         cudaFuncAttributeMaxDynamicSharedMemorySize, SMEMB);
    cudaFuncSetAttribute((const void*)edges_kernel,
                         cudaFuncAttributeMaxDynamicSharedMemorySize, SMEMB);

    // ---- input MLPs: feat = relu(GN(h1@ic_w1) + GN(h2@if_w1)) ----
    mlp0_kernel<<<NN * 32 / 256, 256>>>(ctrs, feats, ic_w0, ic_b0, if_w0, if_b0,
                                        aH, bH);
    gemm_identity<<<256, 256, SMEMB>>>(aH, ic_w1, temp);
    gn_kernel<0><<<NN / 4, 128>>>(temp, ic_g, ic_bt, nullptr, f1, nullptr);
    gemm_identity<<<256, 256, SMEMB>>>(bH, if_w1, temp);
    gn_kernel<2><<<NN / 4, 128>>>(temp, if_g, if_bt, f1, feat, featH);

    // ---- 4 residual fusion blocks ----
    for (int i = 0; i < BBL; i++) {
        gemm_identity<<<256, 256, SMEMB>>>(featH, ctr_w + i * 16384, temp);
        edges_kernel<<<1600, 256, SMEMB>>>(
            featH,
            pre_w + i * SSC * 16384, suc_w + i * SSC * 16384,
            left_w + i * 16384, right_w + i * 16384,
            pre_u, pre_v, suc_u, suc_v, left_u, left_v, right_u, right_v,
            temp);
        gn_kernel<1><<<NN / 4, 128>>>(temp, norm_g + i * 128, norm_b + i * 128,
                                      nullptr, nullptr, aH);
        gemm_identity<<<256, 256, SMEMB>>>(aH, ctr2_w + i * 16384, temp);
        gn_kernel<2><<<NN / 4, 128>>>(temp, ctr2_g + i * 128, ctr2_b + i * 128,
                                      feat, feat, featH);
    }
}